// round 1
// baseline (speedup 1.0000x reference)
#include <cuda_runtime.h>
#include <cstdint>

#define BB 8
#define CC 192
#define HH 128
#define WW 256
#define HWSZ (HH*WW)

#define HT 4
#define WT 64
#define NC 4                      // channels per stage
#define NSTAGE (CC/NC)            // 48
#define THREADS 288               // 9 warps: warp id = displacement row i

#define X1_WORDS (HT*WT)          // 256 floats per channel
#define X2_ROWS (HT+8)            // 12
#define X2_COLS (WT+8)            // 72
#define X2_WORDS (X2_ROWS*X2_COLS)// 864
#define CH_WORDS (X1_WORDS + X2_WORDS)   // 1120
#define VECS_PER_CH (CH_WORDS/4)  // 280
#define X1_VECS (X1_WORDS/4)      // 64
#define TOT_VECS (NC*VECS_PER_CH) // 1120
#define STAGE_WORDS (NC*CH_WORDS) // 4480

// 16B-slot XOR swizzle: kills the 2-way bank conflict from the 8-float pixel
// stride (lanes g and g+4 differ in word-bit5 -> flip word-bit2).
__device__ __forceinline__ int swz(int s) { return s ^ ((s >> 3) & 4); }

__device__ __forceinline__ uint32_t smem_u32(const void* p) {
    return (uint32_t)__cvta_generic_to_shared(p);
}

__device__ __forceinline__ void cp_async16(uint32_t dst, const float* src, int srcsize) {
    asm volatile("cp.async.cg.shared.global [%0], [%1], 16, %2;\n"
                 :: "r"(dst), "l"(src), "r"(srcsize));
}
__device__ __forceinline__ void cp_commit() {
    asm volatile("cp.async.commit_group;\n" ::: "memory");
}
__device__ __forceinline__ void cp_wait_all() {
    asm volatile("cp.async.wait_group 0;\n" ::: "memory");
}

__global__ __launch_bounds__(THREADS, 1)
void costvol_kernel(const float* __restrict__ x1,
                    const float* __restrict__ x2,
                    float* __restrict__ out) {
    __shared__ __align__(16) float smem[2][STAGE_WORDS];

    const int tid  = threadIdx.x;
    const int irow = tid >> 5;        // 0..8  -> di = irow-4
    const int lane = tid & 31;
    const int hl   = lane >> 3;       // 0..3  h within tile
    const int g    = lane & 7;        // 0..7  w-group (8 pixels each)

    const int b  = blockIdx.z;
    const int h0 = blockIdx.y * HT;
    const int w0 = blockIdx.x * WT;

    // ---- precompute staging tasks (pattern fixed per thread; only channel advances) ----
    const float* tsrc[4];
    int tsw[4];
    int tsz[4];
    #pragma unroll
    for (int k = 0; k < 4; ++k) {
        int t = tid + k * THREADS;
        if (t < TOT_VECS) {
            int ch = t / VECS_PER_CH;
            int r  = t - ch * VECS_PER_CH;
            if (r < X1_VECS) {
                int hr = r >> 4;
                int v  = r & 15;
                tsrc[k] = x1 + ((b*CC + ch)*HWSZ) + (h0 + hr)*WW + w0 + 4*v;
                tsw[k]  = ch*CH_WORDS + swz(hr*WT + 4*v);
                tsz[k]  = 16;
            } else {
                int r2  = r - X1_VECS;
                int row = r2 / 18;
                int v   = r2 - row*18;
                int gh  = h0 - 4 + row;
                int gw  = w0 - 4 + 4*v;
                int ok  = (gh >= 0) && (gh < HH) && (gw >= 0) && (gw <= WW-4);
                int ghc = min(max(gh, 0), HH-1);
                int gwc = min(max(gw, 0), WW-4);
                tsrc[k] = x2 + ((b*CC + ch)*HWSZ) + ghc*WW + gwc;
                tsw[k]  = ch*CH_WORDS + X1_WORDS + swz(row*X2_COLS + 4*v);
                tsz[k]  = ok ? 16 : 0;
            }
        } else {
            tsrc[k] = x1;  // dummy
            tsw[k]  = 0;
            tsz[k]  = -1;  // sentinel: skip
        }
    }

    const uint32_t sb0 = smem_u32(&smem[0][0]);
    const uint32_t sb1 = smem_u32(&smem[1][0]);

    // ---- per-thread compute offsets (hoisted swizzles) ----
    const int rr   = hl - irow + 8;                 // x2 halo row 0..11
    const int s1b  = hl*WT + 8*g;
    const int s2b  = rr*X2_COLS + 8*g;
    const int sw1a = swz(s1b),      sw1b = swz(s1b + 4);
    const int sw2a = swz(s2b),      sw2b = swz(s2b + 4);
    const int sw2c = swz(s2b + 8),  sw2d = swz(s2b + 12);

    float acc[9][8];
    #pragma unroll
    for (int j = 0; j < 9; ++j)
        #pragma unroll
        for (int p = 0; p < 8; ++p) acc[j][p] = 0.0f;

    // ---- prologue: stage 0 into buffer 0 ----
    #pragma unroll
    for (int k = 0; k < 4; ++k)
        if (tsz[k] >= 0) cp_async16(sb0 + (uint32_t)tsw[k]*4u, tsrc[k], tsz[k]);
    cp_commit();
    cp_wait_all();
    __syncthreads();

    // ---- main loop: prefetch s+1 while computing s ----
    for (int s = 0; s < NSTAGE; ++s) {
        const int buf = s & 1;
        if (s + 1 < NSTAGE) {
            const uint32_t sbn = (buf ? sb0 : sb1);
            const int adv = (s + 1) * NC * HWSZ;
            #pragma unroll
            for (int k = 0; k < 4; ++k)
                if (tsz[k] >= 0) cp_async16(sbn + (uint32_t)tsw[k]*4u, tsrc[k] + adv, tsz[k]);
            cp_commit();
        }

        const float* sbuf = &smem[buf][0];
        #pragma unroll
        for (int ch = 0; ch < NC; ++ch) {
            const float* p1 = sbuf + ch*CH_WORDS;
            const float* p2 = p1 + X1_WORDS;
            float a[8], v[16];
            *(float4*)(a)    = *(const float4*)(p1 + sw1a);
            *(float4*)(a+4)  = *(const float4*)(p1 + sw1b);
            *(float4*)(v)    = *(const float4*)(p2 + sw2a);
            *(float4*)(v+4)  = *(const float4*)(p2 + sw2b);
            *(float4*)(v+8)  = *(const float4*)(p2 + sw2c);
            *(float4*)(v+12) = *(const float4*)(p2 + sw2d);
            #pragma unroll
            for (int j = 0; j < 9; ++j)
                #pragma unroll
                for (int p = 0; p < 8; ++p)
                    acc[j][p] = fmaf(a[p], v[p + 8 - j], acc[j][p]);
        }

        cp_wait_all();
        __syncthreads();
    }

    // ---- epilogue ----
    const float inv = 1.0f / 81.0f;
    const int h = h0 + hl;
    float* obase = out + (b*81)*HWSZ + h*WW + w0 + 8*g;
    #pragma unroll
    for (int j = 0; j < 9; ++j) {
        int idx = 9*irow + j + 41;      // (9*di + dj) mod 81, di=irow-4, dj=j-4
        if (idx >= 81) idx -= 81;
        float4 o0 = make_float4(acc[j][0]*inv, acc[j][1]*inv, acc[j][2]*inv, acc[j][3]*inv);
        float4 o1 = make_float4(acc[j][4]*inv, acc[j][5]*inv, acc[j][6]*inv, acc[j][7]*inv);
        float* op = obase + idx*HWSZ;
        *(float4*)(op)   = o0;
        *(float4*)(op+4) = o1;
    }
}

extern "C" void kernel_launch(void* const* d_in, const int* in_sizes, int n_in,
                              void* d_out, int out_size) {
    const float* x1 = (const float*)d_in[0];
    const float* x2 = (const float*)d_in[1];
    float* out = (float*)d_out;
    dim3 grid(WW/WT, HH/HT, BB);   // (4, 32, 8)
    dim3 block(THREADS);
    costvol_kernel<<<grid, block>>>(x1, x2, out);
}